// round 1
// baseline (speedup 1.0000x reference)
#include <cuda_runtime.h>
#include <math.h>

#define VV 32000
#define HH 256
#define BB 32
#define TT 128
#define VH (VV + HH)
#define MM (TT * BB)   // 4096 output rows

// Scratch: all hidden states Hn[t][b][h], row index m = t*B + b (matches Ys.reshape(-1,V))
__device__ float g_Hall[(size_t)MM * HH];

__device__ __forceinline__ unsigned tf32_bits(float x) {
    unsigned u;
    asm("cvt.rna.tf32.f32 %0, %1;" : "=r"(u) : "f"(x));
    return u;
}

// ---------------------------------------------------------------------------
// Kernel 1: GRU recurrence. One CTA per batch (32 CTAs x 256 threads).
// Thread i owns hidden dim i. Hidden state lives in SMEM; recurrent weight
// rows are streamed from L2 every step (768KB/step/CTA). Input projections
// are gathered inline (one scattered 4B load per gate per thread per step).
// ---------------------------------------------------------------------------
__global__ __launch_bounds__(256) void rnn_recur(
    const int* __restrict__ X, const float* __restrict__ H0,
    const float* __restrict__ Wz, const float* __restrict__ bz,
    const float* __restrict__ Wr, const float* __restrict__ br,
    const float* __restrict__ Wh, const float* __restrict__ bh,
    float* __restrict__ hf_out, int write_hf)
{
    const int b = blockIdx.x;
    const int i = threadIdx.x;
    __shared__ float sH[HH];
    __shared__ float sRH[HH];

    const float* wzrow = Wz + (size_t)i * VH;
    const float* wrrow = Wr + (size_t)i * VH;
    const float* whrow = Wh + (size_t)i * VH;
    const float4* wz4 = (const float4*)(wzrow + VV);   // recurrent slice, 16B aligned
    const float4* wr4 = (const float4*)(wrrow + VV);
    const float4* wh4 = (const float4*)(whrow + VV);
    const float bzi = bz[i], bri = br[i], bhi = bh[i];

    float hcur = H0[b * HH + i];
    sH[i] = hcur;
    __syncthreads();

    for (int t = 0; t < TT; t++) {
        const int x = X[b * TT + t];
        // inline embedding gathers (issue early; DRAM latency hidden by loop1)
        float gz = __ldg(wzrow + x);
        float gr = __ldg(wrrow + x);
        float gh = __ldg(whrow + x);

        // loop1: z and r matvecs against sH
        float az0=0.f,az1=0.f,az2=0.f,az3=0.f;
        float ar0=0.f,ar1=0.f,ar2=0.f,ar3=0.f;
        const float4* sH4 = (const float4*)sH;
        #pragma unroll 8
        for (int k = 0; k < HH/4; k++) {
            float4 w = wz4[k];
            float4 u = wr4[k];
            float4 h4 = sH4[k];
            az0 += w.x*h4.x; az1 += w.y*h4.y; az2 += w.z*h4.z; az3 += w.w*h4.w;
            ar0 += u.x*h4.x; ar1 += u.y*h4.y; ar2 += u.z*h4.z; ar3 += u.w*h4.w;
        }
        float az = gz + bzi + ((az0+az1)+(az2+az3));
        float ar = gr + bri + ((ar0+ar1)+(ar2+ar3));
        float z = 1.0f / (1.0f + expf(-az));
        float r = 1.0f / (1.0f + expf(-ar));

        sRH[i] = r * hcur;           // (r * Hs) elementwise, dim i
        __syncthreads();             // sRH complete before loop2

        // loop2: h matvec against (r*Hs)
        float ah0=0.f,ah1=0.f,ah2=0.f,ah3=0.f;
        const float4* sRH4 = (const float4*)sRH;
        #pragma unroll 8
        for (int k = 0; k < HH/4; k++) {
            float4 w = wh4[k];
            float4 h4 = sRH4[k];
            ah0 += w.x*h4.x; ah1 += w.y*h4.y; ah2 += w.z*h4.z; ah3 += w.w*h4.w;
        }
        float ah = gh + bhi + ((ah0+ah1)+(ah2+ah3));
        float hv = tanhf(ah);
        float hn = z*hv + (1.0f - z)*hcur;

        g_Hall[((size_t)t*BB + b)*HH + i] = hn;   // coalesced
        sH[i] = hn;                  // safe: all loop1 readers passed earlier barrier
        hcur = hn;
        __syncthreads();             // sH visible + loop2 readers done before next sRH write
    }
    if (write_hf) hf_out[b*HH + i] = hcur;
}

// ---------------------------------------------------------------------------
// Kernel 2: output projection  Y[m,n] = sum_k Hall[m,k] * Wo[n,k] + bo[n]
// M=4096, N=32000, K=256. tf32 mma.sync m16n8k8 (row x col, both K-contiguous).
// CTA tile 128x128, K-chunk 32, 8 warps (4x2), warp tile 32x64.
// SMEM stride padded to 36 floats -> conflict-free fragment LDS + aligned STS.128.
// ---------------------------------------------------------------------------
#define BM 128
#define BN 128
#define BK 32
#define PK 36

__global__ __launch_bounds__(256) void out_gemm(
    const float* __restrict__ Wo, const float* __restrict__ bo,
    float* __restrict__ Y)
{
    __shared__ float As[BM * PK];
    __shared__ float Bs[BN * PK];
    const int m0 = blockIdx.y * BM;
    const int n0 = blockIdx.x * BN;
    const int tid = threadIdx.x;
    const int warp = tid >> 5, lane = tid & 31;
    const int wm = warp >> 1, wn = warp & 1;
    const int g = lane >> 2, tg = lane & 3;

    float c[2][8][4];
    #pragma unroll
    for (int a = 0; a < 2; a++)
        #pragma unroll
        for (int q = 0; q < 8; q++)
            #pragma unroll
            for (int d = 0; d < 4; d++) c[a][q][d] = 0.f;

    const int lrow = tid >> 3;   // 0..31
    const int lc4  = tid & 7;    // float4 column within K-chunk

    for (int kc = 0; kc < HH; kc += BK) {
        #pragma unroll
        for (int j = 0; j < 4; j++) {
            int m = lrow + j * 32;
            float4 va = *(const float4*)(g_Hall + (size_t)(m0 + m) * HH + kc + lc4 * 4);
            va.x = __uint_as_float(tf32_bits(va.x));
            va.y = __uint_as_float(tf32_bits(va.y));
            va.z = __uint_as_float(tf32_bits(va.z));
            va.w = __uint_as_float(tf32_bits(va.w));
            *(float4*)(As + m * PK + lc4 * 4) = va;
            float4 vb = *(const float4*)(Wo + (size_t)(n0 + m) * HH + kc + lc4 * 4);
            vb.x = __uint_as_float(tf32_bits(vb.x));
            vb.y = __uint_as_float(tf32_bits(vb.y));
            vb.z = __uint_as_float(tf32_bits(vb.z));
            vb.w = __uint_as_float(tf32_bits(vb.w));
            *(float4*)(Bs + m * PK + lc4 * 4) = vb;
        }
        __syncthreads();

        #pragma unroll
        for (int kk = 0; kk < BK; kk += 8) {
            unsigned afr[2][4];
            #pragma unroll
            for (int mt = 0; mt < 2; mt++) {
                int rb = wm * 32 + mt * 16;
                afr[mt][0] = __float_as_uint(As[(rb + g    ) * PK + kk + tg    ]);
                afr[mt][1] = __float_as_uint(As[(rb + g + 8) * PK + kk + tg    ]);
                afr[mt][2] = __float_as_uint(As[(rb + g    ) * PK + kk + tg + 4]);
                afr[mt][3] = __float_as_uint(As[(rb + g + 8) * PK + kk + tg + 4]);
            }
            #pragma unroll
            for (int nt = 0; nt < 8; nt++) {
                int cb = wn * 64 + nt * 8;
                unsigned b0 = __float_as_uint(Bs[(cb + g) * PK + kk + tg    ]);
                unsigned b1 = __float_as_uint(Bs[(cb + g) * PK + kk + tg + 4]);
                #pragma unroll
                for (int mt = 0; mt < 2; mt++) {
                    asm volatile(
                        "mma.sync.aligned.m16n8k8.row.col.f32.tf32.tf32.f32 "
                        "{%0,%1,%2,%3}, {%4,%5,%6,%7}, {%8,%9}, {%0,%1,%2,%3};\n"
                        : "+f"(c[mt][nt][0]), "+f"(c[mt][nt][1]),
                          "+f"(c[mt][nt][2]), "+f"(c[mt][nt][3])
                        : "r"(afr[mt][0]), "r"(afr[mt][1]),
                          "r"(afr[mt][2]), "r"(afr[mt][3]),
                          "r"(b0), "r"(b1));
                }
            }
        }
        __syncthreads();
    }

    // epilogue: add bias, store fp32
    #pragma unroll
    for (int mt = 0; mt < 2; mt++) {
        int rr = m0 + wm * 32 + mt * 16 + g;
        #pragma unroll
        for (int nt = 0; nt < 8; nt++) {
            int cc = n0 + wn * 64 + nt * 8 + tg * 2;
            float bo0 = __ldg(bo + cc), bo1 = __ldg(bo + cc + 1);
            Y[(size_t)rr * VV + cc]           = c[mt][nt][0] + bo0;
            Y[(size_t)rr * VV + cc + 1]       = c[mt][nt][1] + bo1;
            Y[(size_t)(rr + 8) * VV + cc]     = c[mt][nt][2] + bo0;
            Y[(size_t)(rr + 8) * VV + cc + 1] = c[mt][nt][3] + bo1;
        }
    }
}

// ---------------------------------------------------------------------------
extern "C" void kernel_launch(void* const* d_in, const int* in_sizes, int n_in,
                              void* d_out, int out_size) {
    const int*   X  = (const int*)  d_in[0];
    const float* H0 = (const float*)d_in[1];
    const float* Wz = (const float*)d_in[2];
    const float* bz = (const float*)d_in[3];
    const float* Wr = (const float*)d_in[4];
    const float* br = (const float*)d_in[5];
    const float* Wh = (const float*)d_in[6];
    const float* bh = (const float*)d_in[7];
    const float* Wo = (const float*)d_in[8];
    const float* bo = (const float*)d_in[9];
    float* Y = (float*)d_out;

    const long long ys_elems = (long long)MM * VV;          // 131,072,000
    int write_hf = ((long long)out_size > ys_elems) ? 1 : 0; // Hf appended after Ys

    rnn_recur<<<BB, HH>>>(X, H0, Wz, bz, Wr, br, Wh, bh, Y + ys_elems, write_hf);

    dim3 grid(VV / BN, MM / BM);   // 250 x 32
    out_gemm<<<grid, 256>>>(Wo, bo, Y);
}

// round 3
// speedup vs baseline: 4.3020x; 4.3020x over previous
#include <cuda_runtime.h>
#include <math.h>

#define VV 32000
#define HH 256
#define BB 32
#define TT 128
#define VH (VV + HH)
#define MM (TT * BB)   // 4096 output rows
#define CR 4           // CTAs per cluster
#define DPC 64         // hidden dims per CTA

// Scratch: all hidden states Hn[t][b][h], row m = t*B + b (matches Ys.reshape(-1,V))
__device__ float g_Hall[(size_t)MM * HH];

__device__ __forceinline__ unsigned tf32_bits(float x) {
    unsigned u;
    asm("cvt.rna.tf32.f32 %0, %1;" : "=r"(u) : "f"(x));
    return u;
}

__device__ __forceinline__ void st_cluster_f32(float* p, int rank, float v) {
    unsigned a = (unsigned)__cvta_generic_to_shared(p);
    unsigned r;
    asm volatile("mapa.shared::cluster.u32 %0, %1, %2;" : "=r"(r) : "r"(a), "r"(rank));
    asm volatile("st.shared::cluster.f32 [%0], %1;" :: "r"(r), "f"(v) : "memory");
}

__device__ __forceinline__ void cluster_sync_all() {
    asm volatile("barrier.cluster.arrive.aligned;" ::: "memory");
    asm volatile("barrier.cluster.wait.aligned;" ::: "memory");
}

// ---------------------------------------------------------------------------
// Kernel 1: GRU recurrence. Cluster of 4 CTAs per batch; CTA owns 64 dims.
// Recurrent weights (3 x 64 x 256 fp32 = 192KB) live in SMEM, k-major with an
// XOR-8 swizzle (conflict-free LDS.128 in compute). Per step: h / r*h vectors
// are exchanged via DSMEM stores + barrier.cluster.
// SMEM floats: wT 49152 | sH 256 | sRH 256 | sG 192 | part 1024 | sX 128
// ---------------------------------------------------------------------------
#define W_FLOATS 49152
#define SM_FLOATS (W_FLOATS + 256 + 256 + 192 + 1024 + 128)
#define SMEM_BYTES (SM_FLOATS * 4)

__global__ void __cluster_dims__(CR, 1, 1) __launch_bounds__(256, 1) rnn_recur(
    const int* __restrict__ X, const float* __restrict__ H0,
    const float* __restrict__ Wz, const float* __restrict__ bz,
    const float* __restrict__ Wr, const float* __restrict__ br,
    const float* __restrict__ Wh, const float* __restrict__ bh,
    float* __restrict__ hf_out, int write_hf)
{
    extern __shared__ float smf[];
    float* wT   = smf;                 // [3][256][64] swizzled
    float* sH   = wT + W_FLOATS;       // full hidden vector (256)
    float* sRH  = sH + 256;            // full r*h vector (256)
    float* sG   = sRH + 256;           // embedding gathers [3][64]
    float* part = sG + 192;            // reduction partials (1024)
    int*   sX   = (int*)(part + 1024); // token ids (128)

    const int tid   = threadIdx.x;
    const int b     = blockIdx.x / CR;
    const int crank = blockIdx.x % CR;
    const int dim0  = DPC * crank;

    // ---- stage recurrent weights into SMEM (transposed k-major + swizzle) ----
    {
        // 3 gates * 64 rows * 64 float4s = 12288 float4 loads
        for (int fid = tid; fid < 3 * 64 * 64; fid += 256) {
            int g = fid >> 12;              // /4096
            int rem = fid & 4095;
            int j = rem >> 6;
            int k4 = rem & 63;
            const float* W = (g == 0) ? Wz : (g == 1) ? Wr : Wh;
            float4 v = *(const float4*)(W + (size_t)(dim0 + j) * VH + VV + k4 * 4);
            float* wg = wT + g * 16384;
            int k = k4 * 4;
            wg[(k    ) * 64 + (j ^ (((k    ) & 7) << 3))] = v.x;
            wg[(k + 1) * 64 + (j ^ (((k + 1) & 7) << 3))] = v.y;
            wg[(k + 2) * 64 + (j ^ (((k + 2) & 7) << 3))] = v.z;
            wg[(k + 3) * 64 + (j ^ (((k + 3) & 7) << 3))] = v.w;
        }
        if (tid < 128) sX[tid] = X[b * TT + tid];
        sH[tid] = H0[b * HH + tid];
    }

    // per-thread persistent registers
    float bias_a = 0.f, bias_h = 0.f;
    if (tid < 128) {
        int g = tid >> 6, j = tid & 63;
        bias_a = (g ? br : bz)[dim0 + j];
    }
    if (tid < 64) bias_h = bh[dim0 + tid];

    __syncthreads();

    float zreg = 0.f;     // gate z, lives in threads 0..63
    float lasth = 0.f;

    for (int t = 0; t < TT; t++) {
        const int x = sX[t];
        // embedding column gathers (global, issued early; hidden by phase A)
        if (tid < 192) {
            int g = tid >> 6, j = tid & 63;
            const float* W = (g == 0) ? Wz : (g == 1) ? Wr : Wh;
            sG[tid] = __ldg(W + (size_t)(dim0 + j) * VH + x);
        }

        // ---- phase A: z and r matvecs over sH ----
        {
            int g = tid >> 7;            // 0:z 1:r
            int s = (tid >> 4) & 7;      // k-split of 32
            int j4 = (tid & 15) << 2;
            const float* wg = wT + g * 16384 + s * 32 * 64;
            float a0 = 0.f, a1 = 0.f, a2 = 0.f, a3 = 0.f;
            #pragma unroll
            for (int kk = 0; kk < 32; kk++) {
                const float4 w = *(const float4*)(wg + kk * 64 + (j4 ^ ((kk & 7) << 3)));
                float hk = sH[s * 32 + kk];
                a0 += w.x * hk; a1 += w.y * hk; a2 += w.z * hk; a3 += w.w * hk;
            }
            *(float4*)(part + (g * 8 + s) * 64 + j4) = make_float4(a0, a1, a2, a3);
        }
        __syncthreads();

        if (tid < 128) {
            int g = tid >> 6, j = tid & 63;
            float a = bias_a + sG[g * 64 + j];
            #pragma unroll
            for (int s = 0; s < 8; s++) a += part[(g * 8 + s) * 64 + j];
            float sig = 1.f / (1.f + __expf(-a));
            if (g == 0) {
                zreg = sig;
            } else {
                float rh = sig * sH[dim0 + j];
                #pragma unroll
                for (int rk = 0; rk < CR; rk++) st_cluster_f32(&sRH[dim0 + j], rk, rh);
            }
        }
        cluster_sync_all();   // rh vectors complete everywhere

        // ---- phase B: h-candidate matvec over sRH ----
        {
            int s2 = tid >> 4;           // k-split of 16
            int j4 = (tid & 15) << 2;
            const float* wg = wT + 2 * 16384 + s2 * 16 * 64;
            float a0 = 0.f, a1 = 0.f, a2 = 0.f, a3 = 0.f;
            #pragma unroll
            for (int kk = 0; kk < 16; kk++) {
                const float4 w = *(const float4*)(wg + kk * 64 + (j4 ^ ((kk & 7) << 3)));
                float hk = sRH[s2 * 16 + kk];
                a0 += w.x * hk; a1 += w.y * hk; a2 += w.z * hk; a3 += w.w * hk;
            }
            *(float4*)(part + s2 * 64 + j4) = make_float4(a0, a1, a2, a3);
        }
        __syncthreads();

        if (tid < 64) {
            int j = tid;
            float a = bias_h + sG[128 + j];
            #pragma unroll
            for (int s = 0; s < 16; s++) a += part[s * 64 + j];
            float e = __expf(2.f * a);
            float hv = (e - 1.f) / (e + 1.f);          // tanh
            float hp = sH[dim0 + j];
            float hn = zreg * hv + (1.f - zreg) * hp;
            g_Hall[((size_t)t * BB + b) * HH + dim0 + j] = hn;
            #pragma unroll
            for (int rk = 0; rk < CR; rk++) st_cluster_f32(&sH[dim0 + j], rk, hn);
            lasth = hn;
        }
        cluster_sync_all();   // h vector complete everywhere
    }

    if (write_hf && tid < 64)
        hf_out[b * HH + dim0 + tid] = lasth;
}

// ---------------------------------------------------------------------------
// Kernel 2: output projection  Y[m,n] = sum_k Hall[m,k] * Wo[n,k] + bo[n]
// M=4096, N=32000, K=256. tf32 mma.sync m16n8k8. (unchanged this round)
// ---------------------------------------------------------------------------
#define BM 128
#define BN 128
#define BK 32
#define PK 36

__global__ __launch_bounds__(256) void out_gemm(
    const float* __restrict__ Wo, const float* __restrict__ bo,
    float* __restrict__ Y)
{
    __shared__ float As[BM * PK];
    __shared__ float Bs[BN * PK];
    const int m0 = blockIdx.y * BM;
    const int n0 = blockIdx.x * BN;
    const int tid = threadIdx.x;
    const int warp = tid >> 5, lane = tid & 31;
    const int wm = warp >> 1, wn = warp & 1;
    const int g = lane >> 2, tg = lane & 3;

    float c[2][8][4];
    #pragma unroll
    for (int a = 0; a < 2; a++)
        #pragma unroll
        for (int q = 0; q < 8; q++)
            #pragma unroll
            for (int d = 0; d < 4; d++) c[a][q][d] = 0.f;

    const int lrow = tid >> 3;
    const int lc4  = tid & 7;

    for (int kc = 0; kc < HH; kc += BK) {
        #pragma unroll
        for (int j = 0; j < 4; j++) {
            int m = lrow + j * 32;
            float4 va = *(const float4*)(g_Hall + (size_t)(m0 + m) * HH + kc + lc4 * 4);
            va.x = __uint_as_float(tf32_bits(va.x));
            va.y = __uint_as_float(tf32_bits(va.y));
            va.z = __uint_as_float(tf32_bits(va.z));
            va.w = __uint_as_float(tf32_bits(va.w));
            *(float4*)(As + m * PK + lc4 * 4) = va;
            float4 vb = *(const float4*)(Wo + (size_t)(n0 + m) * HH + kc + lc4 * 4);
            vb.x = __uint_as_float(tf32_bits(vb.x));
            vb.y = __uint_as_float(tf32_bits(vb.y));
            vb.z = __uint_as_float(tf32_bits(vb.z));
            vb.w = __uint_as_float(tf32_bits(vb.w));
            *(float4*)(Bs + m * PK + lc4 * 4) = vb;
        }
        __syncthreads();

        #pragma unroll
        for (int kk = 0; kk < BK; kk += 8) {
            unsigned afr[2][4];
            #pragma unroll
            for (int mt = 0; mt < 2; mt++) {
                int rb = wm * 32 + mt * 16;
                afr[mt][0] = __float_as_uint(As[(rb + g    ) * PK + kk + tg    ]);
                afr[mt][1] = __float_as_uint(As[(rb + g + 8) * PK + kk + tg    ]);
                afr[mt][2] = __float_as_uint(As[(rb + g    ) * PK + kk + tg + 4]);
                afr[mt][3] = __float_as_uint(As[(rb + g + 8) * PK + kk + tg + 4]);
            }
            #pragma unroll
            for (int nt = 0; nt < 8; nt++) {
                int cb = wn * 64 + nt * 8;
                unsigned b0 = __float_as_uint(Bs[(cb + g) * PK + kk + tg    ]);
                unsigned b1 = __float_as_uint(Bs[(cb + g) * PK + kk + tg + 4]);
                #pragma unroll
                for (int mt = 0; mt < 2; mt++) {
                    asm volatile(
                        "mma.sync.aligned.m16n8k8.row.col.f32.tf32.tf32.f32 "
                        "{%0,%1,%2,%3}, {%4,%5,%6,%7}, {%8,%9}, {%0,%1,%2,%3};\n"
                        : "+f"(c[mt][nt][0]), "+f"(c[mt][nt][1]),
                          "+f"(c[mt][nt][2]), "+f"(c[mt][nt][3])
                        : "r"(afr[mt][0]), "r"(afr[mt][1]),
                          "r"(afr[mt][2]), "r"(afr[mt][3]),
                          "r"(b0), "r"(b1));
                }
            }
        }
        __syncthreads();
    }

    #pragma unroll
    for (int mt = 0; mt < 2; mt++) {
        int rr = m0 + wm * 32 + mt * 16 + g;
        #pragma unroll
        for (int nt = 0; nt < 8; nt++) {
            int cc = n0 + wn * 64 + nt * 8 + tg * 2;
            float bo0 = __ldg(bo + cc), bo1 = __ldg(bo + cc + 1);
            Y[(size_t)rr * VV + cc]           = c[mt][nt][0] + bo0;
            Y[(size_t)rr * VV + cc + 1]       = c[mt][nt][1] + bo1;
            Y[(size_t)(rr + 8) * VV + cc]     = c[mt][nt][2] + bo0;
            Y[(size_t)(rr + 8) * VV + cc + 1] = c[mt][nt][3] + bo1;
        }
    }
}

// ---------------------------------------------------------------------------
extern "C" void kernel_launch(void* const* d_in, const int* in_sizes, int n_in,
                              void* d_out, int out_size) {
    const int*   X  = (const int*)  d_in[0];
    const float* H0 = (const float*)d_in[1];
    const float* Wz = (const float*)d_in[2];
    const float* bz = (const float*)d_in[3];
    const float* Wr = (const float*)d_in[4];
    const float* br = (const float*)d_in[5];
    const float* Wh = (const float*)d_in[6];
    const float* bh = (const float*)d_in[7];
    const float* Wo = (const float*)d_in[8];
    const float* bo = (const float*)d_in[9];
    float* Y = (float*)d_out;

    const long long ys_elems = (long long)MM * VV;
    int write_hf = ((long long)out_size > ys_elems) ? 1 : 0;

    // idempotent, not a stream op (safe under graph capture); no static guard
    cudaFuncSetAttribute(rnn_recur, cudaFuncAttributeMaxDynamicSharedMemorySize,
                         SMEM_BYTES);

    rnn_recur<<<BB * CR, 256, SMEM_BYTES>>>(X, H0, Wz, bz, Wr, br, Wh, bh,
                                            Y + ys_elems, write_hf);

    dim3 grid(VV / BN, MM / BM);   // 250 x 32
    out_gemm<<<grid, 256>>>(Wo, bo, Y);
}

// round 5
// speedup vs baseline: 4.7508x; 1.1043x over previous
#include <cuda_runtime.h>
#include <math.h>

#define VV 32000
#define HH 256
#define BB 32
#define TT 128
#define VH (VV + HH)
#define MM (TT * BB)   // 4096 output rows
#define CR 4           // CTAs per cluster
#define DPC 64         // hidden dims per CTA

// Scratch: all hidden states Hn[t][b][h], row m = t*B + b (matches Ys.reshape(-1,V))
__device__ float g_Hall[(size_t)MM * HH];

__device__ __forceinline__ unsigned tf32_bits(float x) {
    unsigned u;
    asm("cvt.rna.tf32.f32 %0, %1;" : "=r"(u) : "f"(x));
    return u;
}

__device__ __forceinline__ void st_cluster_f32(float* p, int rank, float v) {
    unsigned a = (unsigned)__cvta_generic_to_shared(p);
    unsigned r;
    asm volatile("mapa.shared::cluster.u32 %0, %1, %2;" : "=r"(r) : "r"(a), "r"(rank));
    asm volatile("st.shared::cluster.f32 [%0], %1;" :: "r"(r), "f"(v) : "memory");
}

__device__ __forceinline__ void cluster_sync_all() {
    asm volatile("barrier.cluster.arrive.aligned;" ::: "memory");
    asm volatile("barrier.cluster.wait.aligned;" ::: "memory");
}

// ---------------------------------------------------------------------------
// Kernel 1: GRU recurrence (unchanged — ~355us, known good).
// Cluster of 4 CTAs per batch; CTA owns 64 dims. Weights SMEM-resident.
// ---------------------------------------------------------------------------
#define W_FLOATS 49152
#define SM_FLOATS (W_FLOATS + 256 + 256 + 192 + 1024 + 128)
#define SMEM_BYTES (SM_FLOATS * 4)

__global__ void __cluster_dims__(CR, 1, 1) __launch_bounds__(256, 1) rnn_recur(
    const int* __restrict__ X, const float* __restrict__ H0,
    const float* __restrict__ Wz, const float* __restrict__ bz,
    const float* __restrict__ Wr, const float* __restrict__ br,
    const float* __restrict__ Wh, const float* __restrict__ bh,
    float* __restrict__ hf_out, int write_hf)
{
    extern __shared__ float smf[];
    float* wT   = smf;
    float* sH   = wT + W_FLOATS;
    float* sRH  = sH + 256;
    float* sG   = sRH + 256;
    float* part = sG + 192;
    int*   sX   = (int*)(part + 1024);

    const int tid   = threadIdx.x;
    const int b     = blockIdx.x / CR;
    const int crank = blockIdx.x % CR;
    const int dim0  = DPC * crank;

    {
        for (int fid = tid; fid < 3 * 64 * 64; fid += 256) {
            int g = fid >> 12;
            int rem = fid & 4095;
            int j = rem >> 6;
            int k4 = rem & 63;
            const float* W = (g == 0) ? Wz : (g == 1) ? Wr : Wh;
            float4 v = *(const float4*)(W + (size_t)(dim0 + j) * VH + VV + k4 * 4);
            float* wg = wT + g * 16384;
            int k = k4 * 4;
            wg[(k    ) * 64 + (j ^ (((k    ) & 7) << 3))] = v.x;
            wg[(k + 1) * 64 + (j ^ (((k + 1) & 7) << 3))] = v.y;
            wg[(k + 2) * 64 + (j ^ (((k + 2) & 7) << 3))] = v.z;
            wg[(k + 3) * 64 + (j ^ (((k + 3) & 7) << 3))] = v.w;
        }
        if (tid < 128) sX[tid] = X[b * TT + tid];
        sH[tid] = H0[b * HH + tid];
    }

    float bias_a = 0.f, bias_h = 0.f;
    if (tid < 128) {
        int g = tid >> 6, j = tid & 63;
        bias_a = (g ? br : bz)[dim0 + j];
    }
    if (tid < 64) bias_h = bh[dim0 + tid];

    __syncthreads();

    float zreg = 0.f;
    float lasth = 0.f;

    for (int t = 0; t < TT; t++) {
        const int x = sX[t];
        if (tid < 192) {
            int g = tid >> 6, j = tid & 63;
            const float* W = (g == 0) ? Wz : (g == 1) ? Wr : Wh;
            sG[tid] = __ldg(W + (size_t)(dim0 + j) * VH + x);
        }

        // phase A: z and r matvecs over sH
        {
            int g = tid >> 7;
            int s = (tid >> 4) & 7;
            int j4 = (tid & 15) << 2;
            const float* wg = wT + g * 16384 + s * 32 * 64;
            float a0 = 0.f, a1 = 0.f, a2 = 0.f, a3 = 0.f;
            #pragma unroll
            for (int kk = 0; kk < 32; kk++) {
                const float4 w = *(const float4*)(wg + kk * 64 + (j4 ^ ((kk & 7) << 3)));
                float hk = sH[s * 32 + kk];
                a0 += w.x * hk; a1 += w.y * hk; a2 += w.z * hk; a3 += w.w * hk;
            }
            *(float4*)(part + (g * 8 + s) * 64 + j4) = make_float4(a0, a1, a2, a3);
        }
        __syncthreads();

        if (tid < 128) {
            int g = tid >> 6, j = tid & 63;
            float a = bias_a + sG[g * 64 + j];
            #pragma unroll
            for (int s = 0; s < 8; s++) a += part[(g * 8 + s) * 64 + j];
            float sig = 1.f / (1.f + __expf(-a));
            if (g == 0) {
                zreg = sig;
            } else {
                float rh = sig * sH[dim0 + j];
                #pragma unroll
                for (int rk = 0; rk < CR; rk++) st_cluster_f32(&sRH[dim0 + j], rk, rh);
            }
        }
        cluster_sync_all();

        // phase B: h-candidate matvec over sRH
        {
            int s2 = tid >> 4;
            int j4 = (tid & 15) << 2;
            const float* wg = wT + 2 * 16384 + s2 * 16 * 64;
            float a0 = 0.f, a1 = 0.f, a2 = 0.f, a3 = 0.f;
            #pragma unroll
            for (int kk = 0; kk < 16; kk++) {
                const float4 w = *(const float4*)(wg + kk * 64 + (j4 ^ ((kk & 7) << 3)));
                float hk = sRH[s2 * 16 + kk];
                a0 += w.x * hk; a1 += w.y * hk; a2 += w.z * hk; a3 += w.w * hk;
            }
            *(float4*)(part + s2 * 64 + j4) = make_float4(a0, a1, a2, a3);
        }
        __syncthreads();

        if (tid < 64) {
            int j = tid;
            float a = bias_h + sG[128 + j];
            #pragma unroll
            for (int s = 0; s < 16; s++) a += part[s * 64 + j];
            float e = __expf(2.f * a);
            float hv = (e - 1.f) / (e + 1.f);
            float hp = sH[dim0 + j];
            float hn = zreg * hv + (1.f - zreg) * hp;
            g_Hall[((size_t)t * BB + b) * HH + dim0 + j] = hn;
            #pragma unroll
            for (int rk = 0; rk < CR; rk++) st_cluster_f32(&sH[dim0 + j], rk, hn);
            lasth = hn;
        }
        cluster_sync_all();
    }

    if (write_hf && tid < 64)
        hf_out[b * HH + dim0 + tid] = lasth;
}

// ---------------------------------------------------------------------------
// Kernel 2: output projection  Y[m,n] = sum_k Hall[m,k] * Wo[n,k] + bo[n]
// M=4096, N=32000, K=256. tf32 mma.sync m16n8k8.
// CTA 128x128 with 4 warps, warp tile 64x64 (mt=4, nt=8):
//   1.0 LDS-wavefront per MMA (was 1.5). 2 CTAs/SM co-resident so one CTA's
//   staging overlaps the other's compute.
// ---------------------------------------------------------------------------
#define BM 128
#define BN 128
#define BK 32
#define PK 36

__global__ __launch_bounds__(128, 2) void out_gemm(
    const float* __restrict__ Wo, const float* __restrict__ bo,
    float* __restrict__ Y)
{
    __shared__ float As[BM * PK];
    __shared__ float Bs[BN * PK];
    const int m0 = blockIdx.y * BM;
    const int n0 = blockIdx.x * BN;
    const int tid = threadIdx.x;
    const int warp = tid >> 5, lane = tid & 31;
    const int wm = warp >> 1, wn = warp & 1;        // 2x2 warps, 64x64 tiles
    const int g = lane >> 2, tg = lane & 3;

    float c[4][8][4];
    #pragma unroll
    for (int a = 0; a < 4; a++)
        #pragma unroll
        for (int q = 0; q < 8; q++)
            #pragma unroll
            for (int d = 0; d < 4; d++) c[a][q][d] = 0.f;

    const int lrow = tid >> 3;   // 0..15
    const int lc4  = tid & 7;    // float4 column within K-chunk

    for (int kc = 0; kc < HH; kc += BK) {
        #pragma unroll
        for (int j = 0; j < 8; j++) {
            int m = lrow + j * 16;
            float4 va = *(const float4*)(g_Hall + (size_t)(m0 + m) * HH + kc + lc4 * 4);
            va.x = __uint_as_float(tf32_bits(va.x));
            va.y = __uint_as_float(tf32_bits(va.y));
            va.z = __uint_as_float(tf32_bits(va.z));
            va.w = __uint_as_float(tf32_bits(va.w));
            *(float4*)(As + m * PK + lc4 * 4) = va;
            float4 vb = *(const float4*)(Wo + (size_t)(n0 + m) * HH + kc + lc4 * 4);
            vb.x = __uint_as_float(tf32_bits(vb.x));
            vb.y = __uint_as_float(tf32_bits(vb.y));
            vb.z = __uint_as_float(tf32_bits(vb.z));
            vb.w = __uint_as_float(tf32_bits(vb.w));
            *(float4*)(Bs + m * PK + lc4 * 4) = vb;
        }
        __syncthreads();

        #pragma unroll
        for (int kk = 0; kk < BK; kk += 8) {
            unsigned afr[4][4];
            #pragma unroll
            for (int mt = 0; mt < 4; mt++) {
                int rb = wm * 64 + mt * 16;
                afr[mt][0] = __float_as_uint(As[(rb + g    ) * PK + kk + tg    ]);
                afr[mt][1] = __float_as_uint(As[(rb + g + 8) * PK + kk + tg    ]);
                afr[mt][2] = __float_as_uint(As[(rb + g    ) * PK + kk + tg + 4]);
                afr[mt][3] = __float_as_uint(As[(rb + g + 8) * PK + kk + tg + 4]);
            }
            #pragma unroll
            for (int nt = 0; nt < 8; nt++) {
                int cb = wn * 64 + nt * 8;
                unsigned b0 = __float_as_uint(Bs[(cb + g) * PK + kk + tg    ]);
                unsigned b1 = __float_as_uint(Bs[(cb + g) * PK + kk + tg + 4]);
                #pragma unroll
                for (int mt = 0; mt < 4; mt++) {
                    asm volatile(
                        "mma.sync.aligned.m16n8k8.row.col.f32.tf32.tf32.f32 "
                        "{%0,%1,%2,%3}, {%4,%5,%6,%7}, {%8,%9}, {%0,%1,%2,%3};\n"
                        : "+f"(c[mt][nt][0]), "+f"(c[mt][nt][1]),
                          "+f"(c[mt][nt][2]), "+f"(c[mt][nt][3])
                        : "r"(afr[mt][0]), "r"(afr[mt][1]),
                          "r"(afr[mt][2]), "r"(afr[mt][3]),
                          "r"(b0), "r"(b1));
                }
            }
        }
        __syncthreads();
    }

    // epilogue: add bias, float2 stores
    #pragma unroll
    for (int nt = 0; nt < 8; nt++) {
        int cc = n0 + wn * 64 + nt * 8 + tg * 2;
        float bo0 = __ldg(bo + cc), bo1 = __ldg(bo + cc + 1);
        #pragma unroll
        for (int mt = 0; mt < 4; mt++) {
            int rr = m0 + wm * 64 + mt * 16 + g;
            float2 v0 = make_float2(c[mt][nt][0] + bo0, c[mt][nt][1] + bo1);
            float2 v1 = make_float2(c[mt][nt][2] + bo0, c[mt][nt][3] + bo1);
            *(float2*)(Y + (size_t)rr * VV + cc)       = v0;
            *(float2*)(Y + (size_t)(rr + 8) * VV + cc) = v1;
        }
    }
}

// ---------------------------------------------------------------------------
extern "C" void kernel_launch(void* const* d_in, const int* in_sizes, int n_in,
                              void* d_out, int out_size) {
    const int*   X  = (const int*)  d_in[0];
    const float* H0 = (const float*)d_in[1];
    const float* Wz = (const float*)d_in[2];
    const float* bz = (const float*)d_in[3];
    const float* Wr = (const float*)d_in[4];
    const float* br = (const float*)d_in[5];
    const float* Wh = (const float*)d_in[6];
    const float* bh = (const float*)d_in[7];
    const float* Wo = (const float*)d_in[8];
    const float* bo = (const float*)d_in[9];
    float* Y = (float*)d_out;

    const long long ys_elems = (long long)MM * VV;
    int write_hf = ((long long)out_size > ys_elems) ? 1 : 0;

    cudaFuncSetAttribute(rnn_recur, cudaFuncAttributeMaxDynamicSharedMemorySize,
                         SMEM_BYTES);

    rnn_recur<<<BB * CR, 256, SMEM_BYTES>>>(X, H0, Wz, bz, Wr, br, Wh, bh,
                                            Y + ys_elems, write_hf);

    dim3 grid(VV / BN, MM / BM);   // 250 x 32
    out_gemm<<<grid, 128>>>(Wo, bo, Y);
}

// round 6
// speedup vs baseline: 4.9570x; 1.0434x over previous
#include <cuda_runtime.h>
#include <math.h>

#define VV 32000
#define HH 256
#define BB 32
#define TT 128
#define VH (VV + HH)
#define MM (TT * BB)   // 4096 output rows
#define CR 4           // CTAs per cluster
#define DPC 64         // hidden dims per CTA

// Scratch: hidden states (tf32-rounded) and tf32-rounded copy of Wo
__device__ float g_Hall[(size_t)MM * HH];
__device__ float g_Wo[(size_t)VV * HH];

__device__ __forceinline__ unsigned tf32_bits(float x) {
    unsigned u;
    asm("cvt.rna.tf32.f32 %0, %1;" : "=r"(u) : "f"(x));
    return u;
}
__device__ __forceinline__ float tf32_round(float x) {
    return __uint_as_float(tf32_bits(x));
}

__device__ __forceinline__ void st_cluster_f32(float* p, int rank, float v) {
    unsigned a = (unsigned)__cvta_generic_to_shared(p);
    unsigned r;
    asm volatile("mapa.shared::cluster.u32 %0, %1, %2;" : "=r"(r) : "r"(a), "r"(rank));
    asm volatile("st.shared::cluster.f32 [%0], %1;" :: "r"(r), "f"(v) : "memory");
}

__device__ __forceinline__ void cluster_sync_all() {
    asm volatile("barrier.cluster.arrive.aligned;" ::: "memory");
    asm volatile("barrier.cluster.wait.aligned;" ::: "memory");
}

__device__ __forceinline__ void cp16(unsigned smem_dst, const void* gsrc) {
    asm volatile("cp.async.cg.shared.global [%0], [%1], 16;"
                 :: "r"(smem_dst), "l"(gsrc) : "memory");
}

// ---------------------------------------------------------------------------
// Kernel 0: round Wo to tf32 (rna) once. 2.048M float4s.
// ---------------------------------------------------------------------------
__global__ __launch_bounds__(256) void cvt_wo(const float* __restrict__ Wo) {
    size_t i = ((size_t)blockIdx.x * 256 + threadIdx.x) * 4;
    float4 v = *(const float4*)(Wo + i);
    v.x = tf32_round(v.x); v.y = tf32_round(v.y);
    v.z = tf32_round(v.z); v.w = tf32_round(v.w);
    *(float4*)(g_Wo + i) = v;
}

// ---------------------------------------------------------------------------
// Kernel 1: GRU recurrence (design unchanged; g_Hall now stored tf32-rounded).
// ---------------------------------------------------------------------------
#define W_FLOATS 49152
#define SM_FLOATS (W_FLOATS + 256 + 256 + 192 + 1024 + 128)
#define SMEM_BYTES (SM_FLOATS * 4)

__global__ void __cluster_dims__(CR, 1, 1) __launch_bounds__(256, 1) rnn_recur(
    const int* __restrict__ X, const float* __restrict__ H0,
    const float* __restrict__ Wz, const float* __restrict__ bz,
    const float* __restrict__ Wr, const float* __restrict__ br,
    const float* __restrict__ Wh, const float* __restrict__ bh,
    float* __restrict__ hf_out, int write_hf)
{
    extern __shared__ float smf[];
    float* wT   = smf;
    float* sH   = wT + W_FLOATS;
    float* sRH  = sH + 256;
    float* sG   = sRH + 256;
    float* part = sG + 192;
    int*   sX   = (int*)(part + 1024);

    const int tid   = threadIdx.x;
    const int b     = blockIdx.x / CR;
    const int crank = blockIdx.x % CR;
    const int dim0  = DPC * crank;

    {
        for (int fid = tid; fid < 3 * 64 * 64; fid += 256) {
            int g = fid >> 12;
            int rem = fid & 4095;
            int j = rem >> 6;
            int k4 = rem & 63;
            const float* W = (g == 0) ? Wz : (g == 1) ? Wr : Wh;
            float4 v = *(const float4*)(W + (size_t)(dim0 + j) * VH + VV + k4 * 4);
            float* wg = wT + g * 16384;
            int k = k4 * 4;
            wg[(k    ) * 64 + (j ^ (((k    ) & 7) << 3))] = v.x;
            wg[(k + 1) * 64 + (j ^ (((k + 1) & 7) << 3))] = v.y;
            wg[(k + 2) * 64 + (j ^ (((k + 2) & 7) << 3))] = v.z;
            wg[(k + 3) * 64 + (j ^ (((k + 3) & 7) << 3))] = v.w;
        }
        if (tid < 128) sX[tid] = X[b * TT + tid];
        sH[tid] = H0[b * HH + tid];
    }

    float bias_a = 0.f, bias_h = 0.f;
    if (tid < 128) {
        int g = tid >> 6, j = tid & 63;
        bias_a = (g ? br : bz)[dim0 + j];
    }
    if (tid < 64) bias_h = bh[dim0 + tid];

    __syncthreads();

    float zreg = 0.f;
    float lasth = 0.f;

    for (int t = 0; t < TT; t++) {
        const int x = sX[t];
        if (tid < 192) {
            int g = tid >> 6, j = tid & 63;
            const float* W = (g == 0) ? Wz : (g == 1) ? Wr : Wh;
            sG[tid] = __ldg(W + (size_t)(dim0 + j) * VH + x);
        }

        // phase A: z and r matvecs over sH
        {
            int g = tid >> 7;
            int s = (tid >> 4) & 7;
            int j4 = (tid & 15) << 2;
            const float* wg = wT + g * 16384 + s * 32 * 64;
            float a0 = 0.f, a1 = 0.f, a2 = 0.f, a3 = 0.f;
            #pragma unroll
            for (int kk = 0; kk < 32; kk++) {
                const float4 w = *(const float4*)(wg + kk * 64 + (j4 ^ ((kk & 7) << 3)));
                float hk = sH[s * 32 + kk];
                a0 += w.x * hk; a1 += w.y * hk; a2 += w.z * hk; a3 += w.w * hk;
            }
            *(float4*)(part + (g * 8 + s) * 64 + j4) = make_float4(a0, a1, a2, a3);
        }
        __syncthreads();

        if (tid < 128) {
            int g = tid >> 6, j = tid & 63;
            float a = bias_a + sG[g * 64 + j];
            #pragma unroll
            for (int s = 0; s < 8; s++) a += part[(g * 8 + s) * 64 + j];
            float sig = 1.f / (1.f + __expf(-a));
            if (g == 0) {
                zreg = sig;
            } else {
                float rh = sig * sH[dim0 + j];
                #pragma unroll
                for (int rk = 0; rk < CR; rk++) st_cluster_f32(&sRH[dim0 + j], rk, rh);
            }
        }
        cluster_sync_all();

        // phase B: h-candidate matvec over sRH
        {
            int s2 = tid >> 4;
            int j4 = (tid & 15) << 2;
            const float* wg = wT + 2 * 16384 + s2 * 16 * 64;
            float a0 = 0.f, a1 = 0.f, a2 = 0.f, a3 = 0.f;
            #pragma unroll
            for (int kk = 0; kk < 16; kk++) {
                const float4 w = *(const float4*)(wg + kk * 64 + (j4 ^ ((kk & 7) << 3)));
                float hk = sRH[s2 * 16 + kk];
                a0 += w.x * hk; a1 += w.y * hk; a2 += w.z * hk; a3 += w.w * hk;
            }
            *(float4*)(part + s2 * 64 + j4) = make_float4(a0, a1, a2, a3);
        }
        __syncthreads();

        if (tid < 64) {
            int j = tid;
            float a = bias_h + sG[128 + j];
            #pragma unroll
            for (int s = 0; s < 16; s++) a += part[s * 64 + j];
            float e = __expf(2.f * a);
            float hv = (e - 1.f) / (e + 1.f);
            float hp = sH[dim0 + j];
            float hn = zreg * hv + (1.f - zreg) * hp;
            g_Hall[((size_t)t * BB + b) * HH + dim0 + j] = tf32_round(hn); // pre-round for GEMM
            #pragma unroll
            for (int rk = 0; rk < CR; rk++) st_cluster_f32(&sH[dim0 + j], rk, hn);
            lasth = hn;
        }
        cluster_sync_all();
    }

    if (write_hf && tid < 64)
        hf_out[b * HH + dim0 + tid] = lasth;
}

// ---------------------------------------------------------------------------
// Kernel 2: output projection. CTA 128x128, 4 warps, warp tile 64x64.
// NEW: cp.async 16B staging of pre-rounded tf32 data, 2-stage double buffer
// (next chunk's LDGSTS overlap current chunk's MMAs). No cvt in hot loop.
// ---------------------------------------------------------------------------
#define BM 128
#define BN 128
#define BK 32
#define PK 36
#define TILE_FLOATS (BM * PK)                 // 4608 floats = 18432 B
#define GEMM_SMEM_BYTES (4 * TILE_FLOATS * 4) // 2 stages x (A+B) = 73728 B
#define NCHUNK (HH / BK)                      // 8

__global__ __launch_bounds__(128, 2) void out_gemm(
    const float* __restrict__ bo, float* __restrict__ Y)
{
    extern __shared__ float sm[];
    // layout: [stage0 A][stage0 B][stage1 A][stage1 B]
    const int m0 = blockIdx.y * BM;
    const int n0 = blockIdx.x * BN;
    const int tid = threadIdx.x;
    const int warp = tid >> 5, lane = tid & 31;
    const int wm = warp >> 1, wn = warp & 1;
    const int g = lane >> 2, tg = lane & 3;

    const int lrow = tid >> 3;   // 0..15
    const int lc4  = tid & 7;    // float4 column within K-chunk

    const unsigned smem_base = (unsigned)__cvta_generic_to_shared(sm);

    float c[4][8][4];
    #pragma unroll
    for (int a = 0; a < 4; a++)
        #pragma unroll
        for (int q = 0; q < 8; q++)
            #pragma unroll
            for (int d = 0; d < 4; d++) c[a][q][d] = 0.f;

    // issue one chunk's loads into a stage
    auto issue = [&](int stage, int kc) {
        unsigned sa = smem_base + (unsigned)(stage * 2 * TILE_FLOATS) * 4u;
        unsigned sb = sa + (unsigned)TILE_FLOATS * 4u;
        #pragma unroll
        for (int j = 0; j < 8; j++) {
            int m = lrow + j * 16;
            unsigned off = (unsigned)(m * PK + lc4 * 4) * 4u;
            cp16(sa + off, g_Hall + (size_t)(m0 + m) * HH + kc * BK + lc4 * 4);
            cp16(sb + off, g_Wo   + (size_t)(n0 + m) * HH + kc * BK + lc4 * 4);
        }
        asm volatile("cp.async.commit_group;" ::: "memory");
    };

    issue(0, 0);

    for (int kc = 0; kc < NCHUNK; kc++) {
        if (kc + 1 < NCHUNK) {
            issue((kc + 1) & 1, kc + 1);
            asm volatile("cp.async.wait_group 1;" ::: "memory");
        } else {
            asm volatile("cp.async.wait_group 0;" ::: "memory");
        }
        __syncthreads();

        const float* As = sm + ((kc & 1) * 2) * TILE_FLOATS;
        const float* Bs = As + TILE_FLOATS;

        #pragma unroll
        for (int kk = 0; kk < BK; kk += 8) {
            unsigned afr[4][4];
            #pragma unroll
            for (int mt = 0; mt < 4; mt++) {
                int rb = wm * 64 + mt * 16;
                afr[mt][0] = __float_as_uint(As[(rb + g    ) * PK + kk + tg    ]);
                afr[mt][1] = __float_as_uint(As[(rb + g + 8) * PK + kk + tg    ]);
                afr[mt][2] = __float_as_uint(As[(rb + g    ) * PK + kk + tg + 4]);
                afr[mt][3] = __float_as_uint(As[(rb + g + 8) * PK + kk + tg + 4]);
            }
            #pragma unroll
            for (int nt = 0; nt < 8; nt++) {
                int cb = wn * 64 + nt * 8;
                unsigned b0 = __float_as_uint(Bs[(cb + g) * PK + kk + tg    ]);
                unsigned b1 = __float_as_uint(Bs[(cb + g) * PK + kk + tg + 4]);
                #pragma unroll
                for (int mt = 0; mt < 4; mt++) {
                    asm volatile(
                        "mma.sync.aligned.m16n8k8.row.col.f32.tf32.tf32.f32 "
                        "{%0,%1,%2,%3}, {%4,%5,%6,%7}, {%8,%9}, {%0,%1,%2,%3};\n"
                        : "+f"(c[mt][nt][0]), "+f"(c[mt][nt][1]),
                          "+f"(c[mt][nt][2]), "+f"(c[mt][nt][3])
                        : "r"(afr[mt][0]), "r"(afr[mt][1]),
                          "r"(afr[mt][2]), "r"(afr[mt][3]),
                          "r"(b0), "r"(b1));
                }
            }
        }
        __syncthreads();
    }

    // epilogue: add bias, float2 stores
    #pragma unroll
    for (int nt = 0; nt < 8; nt++) {
        int cc = n0 + wn * 64 + nt * 8 + tg * 2;
        float bo0 = __ldg(bo + cc), bo1 = __ldg(bo + cc + 1);
        #pragma unroll
        for (int mt = 0; mt < 4; mt++) {
            int rr = m0 + wm * 64 + mt * 16 + g;
            float2 v0 = make_float2(c[mt][nt][0] + bo0, c[mt][nt][1] + bo1);
            float2 v1 = make_float2(c[mt][nt][2] + bo0, c[mt][nt][3] + bo1);
            *(float2*)(Y + (size_t)rr * VV + cc)       = v0;
            *(float2*)(Y + (size_t)(rr + 8) * VV + cc) = v1;
        }
    }
}

// ---------------------------------------------------------------------------
extern "C" void kernel_launch(void* const* d_in, const int* in_sizes, int n_in,
                              void* d_out, int out_size) {
    const int*   X  = (const int*)  d_in[0];
    const float* H0 = (const float*)d_in[1];
    const float* Wz = (const float*)d_in[2];
    const float* bz = (const float*)d_in[3];
    const float* Wr = (const float*)d_in[4];
    const float* br = (const float*)d_in[5];
    const float* Wh = (const float*)d_in[6];
    const float* bh = (const float*)d_in[7];
    const float* Wo = (const float*)d_in[8];
    const float* bo = (const float*)d_in[9];
    float* Y = (float*)d_out;

    const long long ys_elems = (long long)MM * VV;
    int write_hf = ((long long)out_size > ys_elems) ? 1 : 0;

    cudaFuncSetAttribute(rnn_recur, cudaFuncAttributeMaxDynamicSharedMemorySize,
                         SMEM_BYTES);
    cudaFuncSetAttribute(out_gemm, cudaFuncAttributeMaxDynamicSharedMemorySize,
                         GEMM_SMEM_BYTES);

    cvt_wo<<<(VV * HH) / (256 * 4), 256>>>(Wo);   // 8192 blocks

    rnn_recur<<<BB * CR, 256, SMEM_BYTES>>>(X, H0, Wz, bz, Wr, br, Wh, bh,
                                            Y + ys_elems, write_hf);

    dim3 grid(VV / BN, MM / BM);   // 250 x 32
    out_gemm<<<grid, 128, GEMM_SMEM_BYTES>>>(bo, Y);
}

// round 9
// speedup vs baseline: 6.4188x; 1.2949x over previous
#include <cuda_runtime.h>
#include <cuda_fp16.h>
#include <math.h>
#include <stdint.h>

#define VV 32000
#define HH 256
#define BB 32
#define TT 128
#define VH (VV + HH)
#define MM (TT * BB)   // 4096 output rows
#define CR 4           // recurrence: CTAs per cluster
#define DPC 64         // hidden dims per CTA

// Scratch: hidden states and Wo, both rounded to fp16 for the output GEMM
__device__ __align__(256) __half g_Hall_h[(size_t)MM * HH];
__device__ __align__(256) __half g_Wo_h[(size_t)VV * HH];

__device__ __forceinline__ void st_cluster_f32(float* p, int rank, float v) {
    unsigned a = (unsigned)__cvta_generic_to_shared(p);
    unsigned r;
    asm volatile("mapa.shared::cluster.u32 %0, %1, %2;" : "=r"(r) : "r"(a), "r"(rank));
    asm volatile("st.shared::cluster.f32 [%0], %1;" :: "r"(r), "f"(v) : "memory");
}

__device__ __forceinline__ void cluster_sync_all() {
    asm volatile("barrier.cluster.arrive.aligned;" ::: "memory");
    asm volatile("barrier.cluster.wait.aligned;" ::: "memory");
}

__device__ __forceinline__ void cp16(unsigned smem_dst, const void* gsrc) {
    asm volatile("cp.async.cg.shared.global [%0], [%1], 16;"
                 :: "r"(smem_dst), "l"(gsrc) : "memory");
}

// ---------------------------------------------------------------------------
// Kernel 0: round Wo to fp16 once (8.192M elements).
// ---------------------------------------------------------------------------
__global__ __launch_bounds__(256) void cvt_wo(const float* __restrict__ Wo) {
    size_t i = ((size_t)blockIdx.x * 256 + threadIdx.x) * 4;
    float4 v = *(const float4*)(Wo + i);
    __half2 h01 = __floats2half2_rn(v.x, v.y);
    __half2 h23 = __floats2half2_rn(v.z, v.w);
    uint2 o;
    o.x = *(const unsigned*)&h01;
    o.y = *(const unsigned*)&h23;
    *(uint2*)(g_Wo_h + i) = o;
}

// ---------------------------------------------------------------------------
// Kernel 1: GRU recurrence (design unchanged; Hall stored fp16 for the GEMM,
// internal state stays fp32).
// ---------------------------------------------------------------------------
#define W_FLOATS 49152
#define SM_FLOATS (W_FLOATS + 256 + 256 + 192 + 1024 + 128)
#define SMEM_BYTES (SM_FLOATS * 4)

__global__ void __cluster_dims__(CR, 1, 1) __launch_bounds__(256, 1) rnn_recur(
    const int* __restrict__ X, const float* __restrict__ H0,
    const float* __restrict__ Wz, const float* __restrict__ bz,
    const float* __restrict__ Wr, const float* __restrict__ br,
    const float* __restrict__ Wh, const float* __restrict__ bh,
    float* __restrict__ hf_out, int write_hf)
{
    extern __shared__ float smf[];
    float* wT   = smf;
    float* sH   = wT + W_FLOATS;
    float* sRH  = sH + 256;
    float* sG   = sRH + 256;
    float* part = sG + 192;
    int*   sX   = (int*)(part + 1024);

    const int tid   = threadIdx.x;
    const int b     = blockIdx.x / CR;
    const int crank = blockIdx.x % CR;
    const int dim0  = DPC * crank;

    {
        for (int fid = tid; fid < 3 * 64 * 64; fid += 256) {
            int g = fid >> 12;
            int rem = fid & 4095;
            int j = rem >> 6;
            int k4 = rem & 63;
            const float* W = (g == 0) ? Wz : (g == 1) ? Wr : Wh;
            float4 v = *(const float4*)(W + (size_t)(dim0 + j) * VH + VV + k4 * 4);
            float* wg = wT + g * 16384;
            int k = k4 * 4;
            wg[(k    ) * 64 + (j ^ (((k    ) & 7) << 3))] = v.x;
            wg[(k + 1) * 64 + (j ^ (((k + 1) & 7) << 3))] = v.y;
            wg[(k + 2) * 64 + (j ^ (((k + 2) & 7) << 3))] = v.z;
            wg[(k + 3) * 64 + (j ^ (((k + 3) & 7) << 3))] = v.w;
        }
        if (tid < 128) sX[tid] = X[b * TT + tid];
        sH[tid] = H0[b * HH + tid];
    }

    float bias_a = 0.f, bias_h = 0.f;
    if (tid < 128) {
        int g = tid >> 6, j = tid & 63;
        bias_a = (g ? br : bz)[dim0 + j];
    }
    if (tid < 64) bias_h = bh[dim0 + tid];

    __syncthreads();

    float zreg = 0.f;
    float lasth = 0.f;

    for (int t = 0; t < TT; t++) {
        const int x = sX[t];
        if (tid < 192) {
            int g = tid >> 6, j = tid & 63;
            const float* W = (g == 0) ? Wz : (g == 1) ? Wr : Wh;
            sG[tid] = __ldg(W + (size_t)(dim0 + j) * VH + x);
        }

        {   // phase A: z and r matvecs over sH
            int g = tid >> 7;
            int s = (tid >> 4) & 7;
            int j4 = (tid & 15) << 2;
            const float* wg = wT + g * 16384 + s * 32 * 64;
            float a0 = 0.f, a1 = 0.f, a2 = 0.f, a3 = 0.f;
            #pragma unroll
            for (int kk = 0; kk < 32; kk++) {
                const float4 w = *(const float4*)(wg + kk * 64 + (j4 ^ ((kk & 7) << 3)));
                float hk = sH[s * 32 + kk];
                a0 += w.x * hk; a1 += w.y * hk; a2 += w.z * hk; a3 += w.w * hk;
            }
            *(float4*)(part + (g * 8 + s) * 64 + j4) = make_float4(a0, a1, a2, a3);
        }
        __syncthreads();

        if (tid < 128) {
            int g = tid >> 6, j = tid & 63;
            float a = bias_a + sG[g * 64 + j];
            #pragma unroll
            for (int s = 0; s < 8; s++) a += part[(g * 8 + s) * 64 + j];
            float sig = 1.f / (1.f + __expf(-a));
            if (g == 0) {
                zreg = sig;
            } else {
                float rh = sig * sH[dim0 + j];
                #pragma unroll
                for (int rk = 0; rk < CR; rk++) st_cluster_f32(&sRH[dim0 + j], rk, rh);
            }
        }
        cluster_sync_all();

        {   // phase B: h-candidate matvec over sRH
            int s2 = tid >> 4;
            int j4 = (tid & 15) << 2;
            const float* wg = wT + 2 * 16384 + s2 * 16 * 64;
            float a0 = 0.f, a1 = 0.f, a2 = 0.f, a3 = 0.f;
            #pragma unroll
            for (int kk = 0; kk < 16; kk++) {
                const float4 w = *(const float4*)(wg + kk * 64 + (j4 ^ ((kk & 7) << 3)));
                float hk = sRH[s2 * 16 + kk];
                a0 += w.x * hk; a1 += w.y * hk; a2 += w.z * hk; a3 += w.w * hk;
            }
            *(float4*)(part + s2 * 64 + j4) = make_float4(a0, a1, a2, a3);
        }
        __syncthreads();

        if (tid < 64) {
            int j = tid;
            float a = bias_h + sG[128 + j];
            #pragma unroll
            for (int s = 0; s < 16; s++) a += part[s * 64 + j];
            float e = __expf(2.f * a);
            float hv = (e - 1.f) / (e + 1.f);
            float hp = sH[dim0 + j];
            float hn = zreg * hv + (1.f - zreg) * hp;
            g_Hall_h[((size_t)t * BB + b) * HH + dim0 + j] = __float2half_rn(hn);
            #pragma unroll
            for (int rk = 0; rk < CR; rk++) st_cluster_f32(&sH[dim0 + j], rk, hn);
            lasth = hn;
        }
        cluster_sync_all();
    }

    if (write_hf && tid < 64)
        hf_out[b * HH + dim0 + tid] = lasth;
}

// ---------------------------------------------------------------------------
// Kernel 2: output projection, fp16 mma.sync.m16n8k16 (f32 accumulate).
// CTA 128x128, 4 warps, warp tile 64x64. BK=64 halves per chunk, 2-stage
// cp.async double buffer. PKH=72-half row stride: conflict-free fragment LDS
// (word = 4g+tg mod 32) and 16B-aligned rows (144B) for cp.async.
// ---------------------------------------------------------------------------
#define BM 128
#define BN 128
#define BKH 64
#define PKH 72
#define TILEH (BM * PKH)                  // 9216 halves = 18432 B per matrix
#define STAGEH (2 * TILEH)                // A+B per stage
#define GEMM_SMEM_BYTES (2 * STAGEH * 2)  // 73728 B
#define NCHUNK (HH / BKH)                 // 4

__global__ __launch_bounds__(128, 2) void out_gemm(
    const float* __restrict__ bo, float* __restrict__ Y)
{
    extern __shared__ __half smh[];
    const int m0 = blockIdx.y * BM;
    const int n0 = blockIdx.x * BN;
    const int tid = threadIdx.x;
    const int warp = tid >> 5, lane = tid & 31;
    const int wm = warp >> 1, wn = warp & 1;
    const int g = lane >> 2, tg = lane & 3;

    const int lrow = tid >> 3;   // 0..15
    const int lc8  = tid & 7;    // 16B column group (8 halves)

    const unsigned smem_base = (unsigned)__cvta_generic_to_shared(smh);

    float c[4][8][4];
    #pragma unroll
    for (int a = 0; a < 4; a++)
        #pragma unroll
        for (int q = 0; q < 8; q++)
            #pragma unroll
            for (int d = 0; d < 4; d++) c[a][q][d] = 0.f;

    auto issue = [&](int stage, int kc) {
        unsigned sa = smem_base + (unsigned)(stage * STAGEH) * 2u;
        unsigned sb = sa + (unsigned)TILEH * 2u;
        #pragma unroll
        for (int j = 0; j < 8; j++) {
            int m = lrow + j * 16;
            unsigned off = (unsigned)(m * PKH + lc8 * 8) * 2u;
            cp16(sa + off, g_Hall_h + (size_t)(m0 + m) * HH + kc * BKH + lc8 * 8);
            cp16(sb + off, g_Wo_h   + (size_t)(n0 + m) * HH + kc * BKH + lc8 * 8);
        }
        asm volatile("cp.async.commit_group;" ::: "memory");
    };

    issue(0, 0);

    for (int kc = 0; kc < NCHUNK; kc++) {
        if (kc + 1 < NCHUNK) {
            issue((kc + 1) & 1, kc + 1);
            asm volatile("cp.async.wait_group 1;" ::: "memory");
        } else {
            asm volatile("cp.async.wait_group 0;" ::: "memory");
        }
        __syncthreads();

        const __half* As = smh + (kc & 1) * STAGEH;
        const __half* Bs = As + TILEH;

        #pragma unroll
        for (int kk = 0; kk < BKH; kk += 16) {
            unsigned afr[4][4];
            #pragma unroll
            for (int mt = 0; mt < 4; mt++) {
                int rb = wm * 64 + mt * 16;
                afr[mt][0] = *(const unsigned*)(As + (rb + g    ) * PKH + kk + 2 * tg    );
                afr[mt][1] = *(const unsigned*)(As + (rb + g + 8) * PKH + kk + 2 * tg    );
                afr[mt][2] = *(const unsigned*)(As + (rb + g    ) * PKH + kk + 2 * tg + 8);
                afr[mt][3] = *(const unsigned*)(As + (rb + g + 8) * PKH + kk + 2 * tg + 8);
            }
            #pragma unroll
            for (int nt = 0; nt < 8; nt++) {
                int cb = wn * 64 + nt * 8;
                unsigned b0 = *(const unsigned*)(Bs + (cb + g) * PKH + kk + 2 * tg    );
                unsigned b1 = *(const unsigned*)(Bs + (cb + g) * PKH + kk + 2 * tg + 8);
                #pragma unroll
                for (int mt = 0; mt < 4; mt++) {
                    asm volatile(
                        "mma.sync.aligned.m16n8k16.row.col.f32.f16.f16.f32 "
                        "{%0,%1,%2,%3}, {%4,%5,%6,%7}, {%8,%9}, {%0,%1,%2,%3};\n"
                        : "+f"(c[mt][nt][0]), "+f"(c[mt][nt][1]),
                          "+f"(c[mt][nt][2]), "+f"(c[mt][nt][3])
                        : "r"(afr[mt][0]), "r"(afr[mt][1]),
                          "r"(afr[mt][2]), "r"(afr[mt][3]),
                          "r"(b0), "r"(b1));
                }
            }
        }
        __syncthreads();
    }

    // epilogue: add bias, float2 stores (same fragment layout as m16n8k8)
    #pragma unroll
    for (int nt = 0; nt < 8; nt++) {
        int cc = n0 + wn * 64 + nt * 8 + tg * 2;
        float bo0 = __ldg(bo + cc), bo1 = __ldg(bo + cc + 1);
        #pragma unroll
        for (int mt = 0; mt < 4; mt++) {
            int rr = m0 + wm * 64 + mt * 16 + g;
            float2 v0 = make_float2(c[mt][nt][0] + bo0, c[mt][nt][1] + bo1);
            float2 v1 = make_float2(c[mt][nt][2] + bo0, c[mt][nt][3] + bo1);
            *(float2*)(Y + (size_t)rr * VV + cc)       = v0;
            *(float2*)(Y + (size_t)(rr + 8) * VV + cc) = v1;
        }
    }
}

// ---------------------------------------------------------------------------
extern "C" void kernel_launch(void* const* d_in, const int* in_sizes, int n_in,
                              void* d_out, int out_size) {
    const int*   X  = (const int*)  d_in[0];
    const float* H0 = (const float*)d_in[1];
    const float* Wz = (const float*)d_in[2];
    const float* bz = (const float*)d_in[3];
    const float* Wr = (const float*)d_in[4];
    const float* br = (const float*)d_in[5];
    const float* Wh = (const float*)d_in[6];
    const float* bh = (const float*)d_in[7];
    const float* Wo = (const float*)d_in[8];
    const float* bo = (const float*)d_in[9];
    float* Y = (float*)d_out;

    const long long ys_elems = (long long)MM * VV;
    int write_hf = ((long long)out_size > ys_elems) ? 1 : 0;

    cudaFuncSetAttribute(rnn_recur, cudaFuncAttributeMaxDynamicSharedMemorySize,
                         SMEM_BYTES);
    cudaFuncSetAttribute(out_gemm, cudaFuncAttributeMaxDynamicSharedMemorySize,
                         GEMM_SMEM_BYTES);

    cvt_wo<<<(VV * HH) / (256 * 4), 256>>>(Wo);

    rnn_recur<<<BB * CR, 256, SMEM_BYTES>>>(X, H0, Wz, bz, Wr, br, Wh, bh,
                                            Y + ys_elems, write_hf);

    dim3 grid(VV / BN, MM / BM);   // 250 x 32
    out_gemm<<<grid, 128, GEMM_SMEM_BYTES>>>(bo, Y);
}